// round 1
// baseline (speedup 1.0000x reference)
#include <cuda_runtime.h>

#define Bn 8
#define Hc 96
#define Wc 128
#define HW (Hc*Wc)
#define CORRC 324

// Scratch (allocation-free rule: __device__ globals)
__device__ float g_cor1[Bn*256*HW];   // conv1x1 output  [B,256,H,W]
__device__ float g_flo1[Bn*128*HW];   // conv7x7 output  [B,128,H,W]
__device__ float g_cat [Bn*256*HW];   // concat(cor2,flo2) [B,256,H,W]

// ---------------------------------------------------------------------------
// 1x1 conv + bias + relu : GEMM [256 x 324] @ [324 x HW] per batch
// block: 128 threads, 256 pixels (2/thread), 32 output channels
// ---------------------------------------------------------------------------
__global__ __launch_bounds__(128) void conv1x1_relu_k(
    const float* __restrict__ in, const float* __restrict__ w,
    const float* __restrict__ bias, float* __restrict__ out)
{
    const int tid = threadIdx.x;
    const int p0 = blockIdx.x * 256 + tid;     // pixel 0 (pixel 1 = p0+128)
    const int coBase = blockIdx.y * 32;
    const int b = blockIdx.z;

    __shared__ float ws[32 * 12];

    float acc0[32], acc1[32];
#pragma unroll
    for (int i = 0; i < 32; i++) { acc0[i] = 0.f; acc1[i] = 0.f; }

    const float* inb = in + (size_t)b * CORRC * HW;

    for (int c0 = 0; c0 < CORRC; c0 += 12) {      // 324 = 27 * 12
        __syncthreads();
#pragma unroll
        for (int i = tid; i < 384; i += 128)
            ws[i] = w[(size_t)(coBase + i / 12) * CORRC + c0 + (i % 12)];
        __syncthreads();

        float x0[12], x1[12];
#pragma unroll
        for (int k = 0; k < 12; k++) {
            const float* pp = inb + (size_t)(c0 + k) * HW;
            x0[k] = pp[p0];
            x1[k] = pp[p0 + 128];
        }
#pragma unroll
        for (int co = 0; co < 32; co++) {
#pragma unroll
            for (int k = 0; k < 12; k++) {
                float wv = ws[co * 12 + k];
                acc0[co] = fmaf(wv, x0[k], acc0[co]);
                acc1[co] = fmaf(wv, x1[k], acc1[co]);
            }
        }
    }

    float* outb = out + (size_t)b * 256 * HW;
#pragma unroll
    for (int co = 0; co < 32; co++) {
        float bv = bias[coBase + co];
        outb[(size_t)(coBase + co) * HW + p0]       = fmaxf(acc0[co] + bv, 0.f);
        outb[(size_t)(coBase + co) * HW + p0 + 128] = fmaxf(acc1[co] + bv, 0.f);
    }
}

// ---------------------------------------------------------------------------
// generic 3x3 conv + bias + relu, pad 1, stride 1
// block: 128 threads (16x8), spatial tile 32x8 (2 px/thread in W), 16 co/block
// out written at channel offset `outChanOff` within a tensor of `outCTotal`
// channels (enables writing the concat buffer / final output directly).
// ---------------------------------------------------------------------------
__global__ __launch_bounds__(128) void conv3x3_relu_k(
    const float* __restrict__ in, int cin,
    const float* __restrict__ w, const float* __restrict__ bias,
    float* __restrict__ out, int coutUsed, int outCTotal, int outChanOff,
    int nCoTiles)
{
    const int tid = threadIdx.x;
    const int tx = tid & 15, ty = tid >> 4;
    const int w0 = blockIdx.x * 32, h0 = blockIdx.y * 8;
    const int coTile = blockIdx.z % nCoTiles;
    const int b = blockIdx.z / nCoTiles;
    const int coBase = coTile * 16;

    __shared__ float st[10][34];
    __shared__ float sw[144];

    float acc[16][2];
#pragma unroll
    for (int i = 0; i < 16; i++) { acc[i][0] = 0.f; acc[i][1] = 0.f; }

    const float* inb = in + (size_t)b * cin * HW;

    for (int ci = 0; ci < cin; ci++) {
        __syncthreads();
        // input tile with 1-px halo: rows h0-1..h0+8, cols w0-1..w0+32
        for (int i = tid; i < 340; i += 128) {
            int r = i / 34, c = i % 34;
            int hh = h0 + r - 1, ww = w0 + c - 1;
            float v = 0.f;
            if ((unsigned)hh < Hc && (unsigned)ww < Wc)
                v = inb[(size_t)ci * HW + hh * Wc + ww];
            st[r][c] = v;
        }
        // 16 co x 9 weights for this ci
        for (int i = tid; i < 144; i += 128) {
            int co = i / 9;
            sw[i] = (coBase + co < coutUsed)
                  ? w[((size_t)(coBase + co) * cin + ci) * 9 + (i % 9)] : 0.f;
        }
        __syncthreads();

        float xv[3][4];
#pragma unroll
        for (int dy = 0; dy < 3; dy++)
#pragma unroll
            for (int dx = 0; dx < 4; dx++)
                xv[dy][dx] = st[ty + dy][2 * tx + dx];

#pragma unroll
        for (int co = 0; co < 16; co++) {
#pragma unroll
            for (int dy = 0; dy < 3; dy++) {
                float a = sw[co * 9 + dy * 3 + 0];
                float bw = sw[co * 9 + dy * 3 + 1];
                float c = sw[co * 9 + dy * 3 + 2];
                acc[co][0] = fmaf(a, xv[dy][0], fmaf(bw, xv[dy][1], fmaf(c, xv[dy][2], acc[co][0])));
                acc[co][1] = fmaf(a, xv[dy][1], fmaf(bw, xv[dy][2], fmaf(c, xv[dy][3], acc[co][1])));
            }
        }
    }

    const int hh = h0 + ty, wwB = w0 + 2 * tx;
    float* outb = out + ((size_t)b * outCTotal + outChanOff) * HW;
#pragma unroll
    for (int co = 0; co < 16; co++) {
        if (coBase + co < coutUsed) {
            float bv = bias[coBase + co];
            float2 v;
            v.x = fmaxf(acc[co][0] + bv, 0.f);
            v.y = fmaxf(acc[co][1] + bv, 0.f);
            *reinterpret_cast<float2*>(&outb[(size_t)(coBase + co) * HW + hh * Wc + wwB]) = v;
        }
    }
}

// ---------------------------------------------------------------------------
// 7x7 conv + bias + relu, pad 3, Cin=2, Cout=128
// block: 256 threads (32x8), 1 px/thread, 16 co/block
// ---------------------------------------------------------------------------
__global__ __launch_bounds__(256) void conv7x7_relu_k(
    const float* __restrict__ in, const float* __restrict__ w,
    const float* __restrict__ bias, float* __restrict__ out)
{
    const int tid = threadIdx.x;
    const int tx = tid & 31, ty = tid >> 5;
    const int w0 = blockIdx.x * 32, h0 = blockIdx.y * 8;
    const int coTile = blockIdx.z & 7;
    const int b = blockIdx.z >> 3;
    const int coBase = coTile * 16;

    __shared__ float st[2][14][38];   // 2 ci, 8+6 rows, 32+6 cols
    __shared__ float sw[16 * 2 * 49]; // 1568 weights for this co tile

    const float* inb = in + (size_t)b * 2 * HW;
    for (int i = tid; i < 2 * 14 * 38; i += 256) {
        int ci = i / 532, r = (i % 532) / 38, c = i % 38;
        int hh = h0 + r - 3, ww = w0 + c - 3;
        float v = 0.f;
        if ((unsigned)hh < Hc && (unsigned)ww < Wc)
            v = inb[(size_t)ci * HW + hh * Wc + ww];
        st[ci][r][c] = v;
    }
    for (int i = tid; i < 1568; i += 256)
        sw[i] = w[(size_t)coBase * 98 + i];   // [co][ci][7][7], 98 floats/co
    __syncthreads();

    float acc[16];
#pragma unroll
    for (int i = 0; i < 16; i++) acc[i] = 0.f;

#pragma unroll
    for (int ci = 0; ci < 2; ci++) {
#pragma unroll
        for (int dy = 0; dy < 7; dy++) {
            float xv[7];
#pragma unroll
            for (int k = 0; k < 7; k++) xv[k] = st[ci][ty + dy][tx + k];
#pragma unroll
            for (int co = 0; co < 16; co++) {
#pragma unroll
                for (int dx = 0; dx < 7; dx++)
                    acc[co] = fmaf(sw[co * 98 + ci * 49 + dy * 7 + dx], xv[dx], acc[co]);
            }
        }
    }

    const int hh = h0 + ty, ww = w0 + tx;
    float* outb = out + (size_t)b * 128 * HW;
#pragma unroll
    for (int co = 0; co < 16; co++)
        outb[(size_t)(coBase + co) * HW + hh * Wc + ww] =
            fmaxf(acc[co] + bias[coBase + co], 0.f);
}

// append flow into output channels 126..127
__global__ void concat_flow_k(const float* __restrict__ flow, float* __restrict__ out)
{
    int i = blockIdx.x * 256 + threadIdx.x;
    if (i < Bn * 2 * HW) {
        int b = i / (2 * HW);
        int r = i % (2 * HW);
        out[(size_t)b * 128 * HW + (size_t)126 * HW + r] = flow[i];
    }
}

extern "C" void kernel_launch(void* const* d_in, const int* in_sizes, int n_in,
                              void* d_out, int out_size)
{
    const float* flow = (const float*)d_in[0];
    const float* corr = (const float*)d_in[1];
    const float* wc1  = (const float*)d_in[2];
    const float* bc1  = (const float*)d_in[3];
    const float* wc2  = (const float*)d_in[4];
    const float* bc2  = (const float*)d_in[5];
    const float* wf1  = (const float*)d_in[6];
    const float* bf1  = (const float*)d_in[7];
    const float* wf2  = (const float*)d_in[8];
    const float* bf2  = (const float*)d_in[9];
    const float* wo   = (const float*)d_in[10];
    const float* bo   = (const float*)d_in[11];
    float* out = (float*)d_out;

    float *cor1, *flo1, *cat;
    cudaGetSymbolAddress((void**)&cor1, g_cor1);
    cudaGetSymbolAddress((void**)&flo1, g_flo1);
    cudaGetSymbolAddress((void**)&cat,  g_cat);

    // cor = relu(conv1x1(corr))           [B,256,H,W]
    conv1x1_relu_k<<<dim3(HW / 256, 256 / 32, Bn), 128>>>(corr, wc1, bc1, cor1);
    // flo = relu(conv7x7(flow))           [B,128,H,W]
    conv7x7_relu_k<<<dim3(Wc / 32, Hc / 8, Bn * 8), 256>>>(flow, wf1, bf1, flo1);
    // cor = relu(conv3x3(cor)) -> cat[:,0:192]
    conv3x3_relu_k<<<dim3(Wc / 32, Hc / 8, Bn * 12), 128>>>(cor1, 256, wc2, bc2, cat, 192, 256, 0, 12);
    // flo = relu(conv3x3(flo)) -> cat[:,192:256]
    conv3x3_relu_k<<<dim3(Wc / 32, Hc / 8, Bn * 4), 128>>>(flo1, 128, wf2, bf2, cat, 64, 256, 192, 4);
    // out = relu(conv3x3(cat)) -> d_out[:,0:126]
    conv3x3_relu_k<<<dim3(Wc / 32, Hc / 8, Bn * 8), 128>>>(cat, 256, wo, bo, out, 126, 128, 0, 8);
    // d_out[:,126:128] = flow
    concat_flow_k<<<(Bn * 2 * HW + 255) / 256, 256>>>(flow, out);
}